// round 1
// baseline (speedup 1.0000x reference)
#include <cuda_runtime.h>
#include <cstdint>

// Problem constants
#define NTOK   32768          // B*S = 8*4096
#define DBASE  512
#define DF     32
#define SMP    36             // padded smem row (floats), multiple of 4 for float4

// Output layout (floats): base | fiber | connection | generators
#define OUT_BASE   ((size_t)0)
#define OUT_FIBER  ((size_t)NTOK * DBASE)                       // 16777216
#define OUT_CONN   (OUT_FIBER + (size_t)NTOK * 1024)            // 50331648
#define OUT_GEN    (OUT_CONN + (size_t)NTOK * 8)                // 50593792

__global__ __launch_bounds__(256) void fiber_bundle_kernel(
    const int*   __restrict__ tokens,
    const float* __restrict__ base_w,
    const float* __restrict__ fiber_w,
    const float* __restrict__ conn_w,
    const float* __restrict__ gen,
    float*       __restrict__ out)
{
    // 4 matrices per block, 64 threads per matrix.
    __shared__ float sm[4][3][32 * SMP];   // [matrix][Xs, XTs, Ts]

    const int tid = threadIdx.x;
    const int m   = tid >> 6;      // matrix group in block: 0..3
    const int gt  = tid & 63;      // thread within group
    const int it  = gt >> 3;       // row-tile index 0..7 (rows 4*it..4*it+3)
    const int jq  = gt & 7;        // col-tile index 0..7 (cols 4*jq..4*jq+3)

    const int tokIdx = blockIdx.x * 4 + m;
    const int tok    = tokens[tokIdx];

    float* Xs  = sm[m][0];
    float* XTs = sm[m][1];
    float* Ts  = sm[m][2];

    // ---- load 4x4 fiber tile ----
    float c[4][4];
    const float* fsrc = fiber_w + (size_t)tok * 1024;
    #pragma unroll
    for (int r = 0; r < 4; r++) {
        float4 v = *(const float4*)(fsrc + (4 * it + r) * 32 + 4 * jq);
        c[r][0] = v.x; c[r][1] = v.y; c[r][2] = v.z; c[r][3] = v.w;
    }

    // write X (row-major) and X^T into smem
    #pragma unroll
    for (int r = 0; r < 4; r++)
        *(float4*)(Xs + (4 * it + r) * SMP + 4 * jq) =
            make_float4(c[r][0], c[r][1], c[r][2], c[r][3]);
    #pragma unroll
    for (int q = 0; q < 4; q++)
        *(float4*)(XTs + (4 * jq + q) * SMP + 4 * it) =
            make_float4(c[0][q], c[1][q], c[2][q], c[3][q]);
    __syncthreads();

    // ---- Newton-Schulz: X <- 0.5 * X * (3I - X^T X), 3 iterations ----
    #pragma unroll 1
    for (int iter = 0; iter < 3; iter++) {
        // A tile = (X^T X)[4it.., 4jq..] : per k read row k of X twice (float4)
        float a[4][4];
        #pragma unroll
        for (int r = 0; r < 4; r++)
            #pragma unroll
            for (int q = 0; q < 4; q++) a[r][q] = 0.0f;

        #pragma unroll
        for (int k = 0; k < 32; k++) {
            float4 p4 = *(const float4*)(Xs + k * SMP + 4 * it);
            float4 q4 = *(const float4*)(Xs + k * SMP + 4 * jq);
            float pr[4] = {p4.x, p4.y, p4.z, p4.w};
            float qc[4] = {q4.x, q4.y, q4.z, q4.w};
            #pragma unroll
            for (int r = 0; r < 4; r++)
                #pragma unroll
                for (int q = 0; q < 4; q++)
                    a[r][q] += pr[r] * qc[q];
        }

        // T = 3I - A, write tile to Ts
        #pragma unroll
        for (int r = 0; r < 4; r++) {
            float t0 = -a[r][0], t1 = -a[r][1], t2 = -a[r][2], t3 = -a[r][3];
            if (it == jq) {           // tile straddles the diagonal
                if (r == 0) t0 += 3.0f;
                if (r == 1) t1 += 3.0f;
                if (r == 2) t2 += 3.0f;
                if (r == 3) t3 += 3.0f;
            }
            *(float4*)(Ts + (4 * it + r) * SMP + 4 * jq) = make_float4(t0, t1, t2, t3);
        }
        __syncthreads();

        // C tile = (X * T)[4it.., 4jq..] : X[i][k] = XT[k][i] (row-contig float4)
        #pragma unroll
        for (int r = 0; r < 4; r++)
            #pragma unroll
            for (int q = 0; q < 4; q++) c[r][q] = 0.0f;

        #pragma unroll
        for (int k = 0; k < 32; k++) {
            float4 p4 = *(const float4*)(XTs + k * SMP + 4 * it);
            float4 q4 = *(const float4*)(Ts  + k * SMP + 4 * jq);
            float pr[4] = {p4.x, p4.y, p4.z, p4.w};
            float qc[4] = {q4.x, q4.y, q4.z, q4.w};
            #pragma unroll
            for (int r = 0; r < 4; r++)
                #pragma unroll
                for (int q = 0; q < 4; q++)
                    c[r][q] += pr[r] * qc[q];
        }
        #pragma unroll
        for (int r = 0; r < 4; r++)
            #pragma unroll
            for (int q = 0; q < 4; q++) c[r][q] *= 0.5f;

        if (iter < 2) {
            __syncthreads();   // all Ts/XTs reads done before overwrite
            #pragma unroll
            for (int r = 0; r < 4; r++)
                *(float4*)(Xs + (4 * it + r) * SMP + 4 * jq) =
                    make_float4(c[r][0], c[r][1], c[r][2], c[r][3]);
            #pragma unroll
            for (int q = 0; q < 4; q++)
                *(float4*)(XTs + (4 * jq + q) * SMP + 4 * it) =
                    make_float4(c[0][q], c[1][q], c[2][q], c[3][q]);
            __syncthreads();
        }
    }

    // ---- write fiber output ----
    float* fdst = out + OUT_FIBER + (size_t)tokIdx * 1024;
    #pragma unroll
    for (int r = 0; r < 4; r++)
        *(float4*)(fdst + (4 * it + r) * 32 + 4 * jq) =
            make_float4(c[r][0], c[r][1], c[r][2], c[r][3]);

    // ---- base embedding copy: 512 floats = 128 float4, 64 threads -> 2 each ----
    {
        const float4* src = (const float4*)(base_w + (size_t)tok * DBASE);
        float4*       dst = (float4*)(out + OUT_BASE + (size_t)tokIdx * DBASE);
        dst[gt]      = src[gt];
        dst[gt + 64] = src[gt + 64];
    }

    // ---- connection copy: 8 floats ----
    if (gt < 8)
        out[OUT_CONN + (size_t)tokIdx * 8 + gt] = conn_w[(size_t)tok * 8 + gt];

    // ---- generators copy: 8192 floats, blocks 0..7 copy 1024 each (float4) ----
    if (blockIdx.x < 8) {
        const float4* src = (const float4*)gen;
        float4*       dst = (float4*)(out + OUT_GEN);
        int idx = blockIdx.x * 256 + tid;   // 2048 float4 total
        dst[idx] = src[idx];
    }
}

extern "C" void kernel_launch(void* const* d_in, const int* in_sizes, int n_in,
                              void* d_out, int out_size)
{
    const int*   tokens  = (const int*)  d_in[0];
    const float* base_w  = (const float*)d_in[1];
    const float* fiber_w = (const float*)d_in[2];
    const float* conn_w  = (const float*)d_in[3];
    const float* gen     = (const float*)d_in[4];
    float* out = (float*)d_out;

    dim3 grid(NTOK / 4);   // 8192 blocks, 4 matrices each
    dim3 block(256);
    fiber_bundle_kernel<<<grid, block>>>(tokens, base_w, fiber_w, conn_w, gen, out);
}

// round 2
// speedup vs baseline: 1.1845x; 1.1845x over previous
#include <cuda_runtime.h>
#include <cstdint>

// ---------------- problem constants ----------------
#define NTOK   32768                 // B*S
#define OUT_FIBER  ((size_t)NTOK * 512)
#define OUT_CONN   (OUT_FIBER + (size_t)NTOK * 1024)
#define OUT_GEN    (OUT_CONN + (size_t)NTOK * 8)

#define MATS   8                     // matrices per block (128 threads, 16/matrix)
#define BUFF   1184                  // floats per smem buffer (32 rows, padded+swizzle slack)
#define SMEM_BYTES (MATS * 2 * BUFF * 4)   // 75776 B

typedef unsigned long long u64;

// swizzled row offset (floats): stride 36, +4 floats per 8-row group
__device__ __forceinline__ int rowF(int row) { return row * 36 + ((row >> 3) << 2); }

__device__ __forceinline__ u64 pk2(float lo, float hi) {
    u64 r; asm("mov.b64 %0,{%1,%2};" : "=l"(r) : "f"(lo), "f"(hi)); return r;
}
__device__ __forceinline__ void upk2(u64 v, float &lo, float &hi) {
    asm("mov.b64 {%0,%1},%2;" : "=f"(lo), "=f"(hi) : "l"(v));
}
__device__ __forceinline__ u64 ffma2(u64 a, u64 b, u64 c) {
    u64 d; asm("fma.rn.f32x2 %0,%1,%2,%3;" : "=l"(d) : "l"(a), "l"(b), "l"(c)); return d;
}
__device__ __forceinline__ void lds_p2(const float* p, u64 &a, u64 &b) {
    unsigned s = (unsigned)__cvta_generic_to_shared(p);
    asm volatile("ld.shared.v2.u64 {%0,%1},[%2];" : "=l"(a), "=l"(b) : "r"(s));
}
__device__ __forceinline__ void lds_f4(const float* p, float &x, float &y, float &z, float &w) {
    unsigned s = (unsigned)__cvta_generic_to_shared(p);
    asm volatile("ld.shared.v4.f32 {%0,%1,%2,%3},[%4];" : "=f"(x), "=f"(y), "=f"(z), "=f"(w) : "r"(s));
}
__device__ __forceinline__ void sts_p2(float* p, u64 a, u64 b) {
    unsigned s = (unsigned)__cvta_generic_to_shared(p);
    asm volatile("st.shared.v2.u64 [%0],{%1,%2};" :: "r"(s), "l"(a), "l"(b));
}
__device__ __forceinline__ void sts_f4(float* p, float x, float y, float z, float w) {
    unsigned s = (unsigned)__cvta_generic_to_shared(p);
    asm volatile("st.shared.v4.f32 [%0],{%1,%2,%3,%4};" :: "r"(s), "f"(x), "f"(y), "f"(z), "f"(w));
}

// C[8x8 tile] += P^T-slice * Q-slice:  acc[r][q2] (pair over q) over k=0..31
// splat side: scalar pSrc[rowF(k) + 8*it + r]; pair side: qSrc[rowF(k) + 8*jq + 2*q2..]
__device__ __forceinline__ void mm32(const float* __restrict__ pSrc,
                                     const float* __restrict__ qSrc,
                                     int it, int jq, u64 acc[8][4])
{
    const int po = 8 * it, qo = 8 * jq;
    #pragma unroll 4
    for (int k = 0; k < 32; k++) {
        const float* pr = pSrc + rowF(k) + po;
        const float* qr = qSrc + rowF(k) + qo;
        float p0,p1,p2,p3,p4,p5,p6,p7;
        lds_f4(pr,     p0, p1, p2, p3);
        lds_f4(pr + 4, p4, p5, p6, p7);
        u64 q0, q1, q2, q3;
        lds_p2(qr,     q0, q1);
        lds_p2(qr + 4, q2, q3);
        float ps[8] = {p0,p1,p2,p3,p4,p5,p6,p7};
        #pragma unroll
        for (int r = 0; r < 8; r++) {
            u64 sp = pk2(ps[r], ps[r]);
            acc[r][0] = ffma2(sp, q0, acc[r][0]);
            acc[r][1] = ffma2(sp, q1, acc[r][1]);
            acc[r][2] = ffma2(sp, q2, acc[r][2]);
            acc[r][3] = ffma2(sp, q3, acc[r][3]);
        }
    }
}

__global__ __launch_bounds__(128) void fiber_bundle_kernel(
    const int*   __restrict__ tokens,
    const float* __restrict__ base_w,
    const float* __restrict__ fiber_w,
    const float* __restrict__ conn_w,
    const float* __restrict__ gen,
    float*       __restrict__ out)
{
    extern __shared__ float sm[];

    const int tid = threadIdx.x;
    const int m   = tid >> 4;          // matrix 0..7
    const int t   = tid & 15;          // thread in matrix
    const int it  = t >> 2;            // row-tile 0..3 (rows 8*it..)
    const int jq  = t & 3;             // col-tile 0..3 (cols 8*jq..)

    float* B1 = sm + m * (2 * BUFF);   // X, then T', then new X
    float* B2 = B1 + BUFF;             // X^T

    const int tokIdx = blockIdx.x * MATS + m;
    const int tok    = tokens[tokIdx];

    // ---- load 8x8 fiber tile from gmem; write X to B1 and X^T to B2 ----
    float c[8][8];
    {
        const float* fsrc = fiber_w + (size_t)tok * 1024;
        #pragma unroll
        for (int r = 0; r < 8; r++) {
            float4 a = *(const float4*)(fsrc + (8 * it + r) * 32 + 8 * jq);
            float4 b = *(const float4*)(fsrc + (8 * it + r) * 32 + 8 * jq + 4);
            c[r][0]=a.x; c[r][1]=a.y; c[r][2]=a.z; c[r][3]=a.w;
            c[r][4]=b.x; c[r][5]=b.y; c[r][6]=b.z; c[r][7]=b.w;
        }
        #pragma unroll
        for (int r = 0; r < 8; r++) {
            float* d = B1 + rowF(8 * it + r) + 8 * jq;
            sts_f4(d,     c[r][0], c[r][1], c[r][2], c[r][3]);
            sts_f4(d + 4, c[r][4], c[r][5], c[r][6], c[r][7]);
        }
        #pragma unroll
        for (int s = 0; s < 8; s++) {
            float* d = B2 + rowF(8 * jq + s) + 8 * it;
            sts_f4(d,     c[0][s], c[1][s], c[2][s], c[3][s]);
            sts_f4(d + 4, c[4][s], c[5][s], c[6][s], c[7][s]);
        }
    }

    // ---- base embedding copy (overlaps with smem waits): 512 floats / 16 thr ----
    {
        const float4* src = (const float4*)(base_w + (size_t)tok * 512);
        float4*       dst = (float4*)(out + (size_t)tokIdx * 512);
        #pragma unroll
        for (int j = 0; j < 8; j++) dst[t + 16 * j] = src[t + 16 * j];
    }
    if (t < 8)
        out[OUT_CONN + (size_t)tokIdx * 8 + t] = conn_w[(size_t)tok * 8 + t];
    if (blockIdx.x < 16) {
        const float4* src = (const float4*)gen;
        float4*       dst = (float4*)(out + OUT_GEN);
        dst[blockIdx.x * 128 + tid] = src[blockIdx.x * 128 + tid];
    }

    __syncthreads();

    const u64 NEGH = pk2(-0.5f, -0.5f);
    u64 acc[8][4];

    // ---- 3 Newton-Schulz iterations: X <- X * (1.5I - 0.5 X^T X) ----
    #pragma unroll 1
    for (int iter = 0; iter < 3; iter++) {
        // mm1: A = X^T X  (both operand slices from rows of B1=X)
        #pragma unroll
        for (int r = 0; r < 8; r++)
            #pragma unroll
            for (int q = 0; q < 4; q++) acc[r][q] = 0ull;
        mm32(B1, B1, it, jq, acc);

        __syncthreads();
        // write T' = 1.5I - 0.5A into B1
        #pragma unroll
        for (int r = 0; r < 8; r++) {
            u64 t0, t1, t2, t3;
            {
                float dl, dh;
                dl = (it == jq && r == 0) ? 1.5f : 0.0f;
                dh = (it == jq && r == 1) ? 1.5f : 0.0f;
                t0 = ffma2(acc[r][0], NEGH, pk2(dl, dh));
                dl = (it == jq && r == 2) ? 1.5f : 0.0f;
                dh = (it == jq && r == 3) ? 1.5f : 0.0f;
                t1 = ffma2(acc[r][1], NEGH, pk2(dl, dh));
                dl = (it == jq && r == 4) ? 1.5f : 0.0f;
                dh = (it == jq && r == 5) ? 1.5f : 0.0f;
                t2 = ffma2(acc[r][2], NEGH, pk2(dl, dh));
                dl = (it == jq && r == 6) ? 1.5f : 0.0f;
                dh = (it == jq && r == 7) ? 1.5f : 0.0f;
                t3 = ffma2(acc[r][3], NEGH, pk2(dl, dh));
            }
            float* d = B1 + rowF(8 * it + r) + 8 * jq;
            sts_p2(d,     t0, t1);
            sts_p2(d + 4, t2, t3);
        }
        __syncthreads();

        // mm2: C = X * T'  (splat side = B2=X^T rows, pair side = B1=T' rows)
        #pragma unroll
        for (int r = 0; r < 8; r++)
            #pragma unroll
            for (int q = 0; q < 4; q++) acc[r][q] = 0ull;
        mm32(B2, B1, it, jq, acc);

        if (iter < 2) {
            __syncthreads();
            // new X into B1 (pairs are already final values)
            #pragma unroll
            for (int r = 0; r < 8; r++) {
                float* d = B1 + rowF(8 * it + r) + 8 * jq;
                sts_p2(d,     acc[r][0], acc[r][1]);
                sts_p2(d + 4, acc[r][2], acc[r][3]);
            }
            // unpack and write new X^T into B2
            #pragma unroll
            for (int r = 0; r < 8; r++)
                #pragma unroll
                for (int q = 0; q < 4; q++)
                    upk2(acc[r][q], c[r][2 * q], c[r][2 * q + 1]);
            #pragma unroll
            for (int s = 0; s < 8; s++) {
                float* d = B2 + rowF(8 * jq + s) + 8 * it;
                sts_f4(d,     c[0][s], c[1][s], c[2][s], c[3][s]);
                sts_f4(d + 4, c[4][s], c[5][s], c[6][s], c[7][s]);
            }
            __syncthreads();
        }
    }

    // ---- write fiber output ----
    {
        float* fdst = out + OUT_FIBER + (size_t)tokIdx * 1024;
        #pragma unroll
        for (int r = 0; r < 8; r++) {
            float x0,x1,x2,x3,x4,x5,x6,x7;
            upk2(acc[r][0], x0, x1);
            upk2(acc[r][1], x2, x3);
            upk2(acc[r][2], x4, x5);
            upk2(acc[r][3], x6, x7);
            float* d = fdst + (8 * it + r) * 32 + 8 * jq;
            *(float4*)d       = make_float4(x0, x1, x2, x3);
            *(float4*)(d + 4) = make_float4(x4, x5, x6, x7);
        }
    }
}

extern "C" void kernel_launch(void* const* d_in, const int* in_sizes, int n_in,
                              void* d_out, int out_size)
{
    const int*   tokens  = (const int*)  d_in[0];
    const float* base_w  = (const float*)d_in[1];
    const float* fiber_w = (const float*)d_in[2];
    const float* conn_w  = (const float*)d_in[3];
    const float* gen     = (const float*)d_in[4];
    float* out = (float*)d_out;

    cudaFuncSetAttribute(fiber_bundle_kernel,
                         cudaFuncAttributeMaxDynamicSharedMemorySize, SMEM_BYTES);

    dim3 grid(NTOK / MATS);   // 4096 blocks, 8 matrices each
    dim3 block(128);
    fiber_bundle_kernel<<<grid, block, SMEM_BYTES>>>(tokens, base_w, fiber_w, conn_w, gen, out);
}

// round 3
// speedup vs baseline: 1.2431x; 1.0495x over previous
#include <cuda_runtime.h>
#include <cstdint>

// ---------------- problem constants ----------------
#define NTOK   32768                 // B*S
#define OUT_FIBER  ((size_t)NTOK * 512)
#define OUT_CONN   (OUT_FIBER + (size_t)NTOK * 1024)
#define OUT_GEN    (OUT_CONN + (size_t)NTOK * 8)

typedef unsigned long long u64;

// ---------------- packed fp32x2 helpers ----------------
__device__ __forceinline__ u64 pk2(float lo, float hi) {
    u64 r; asm("mov.b64 %0,{%1,%2};" : "=l"(r) : "f"(lo), "f"(hi)); return r;
}
__device__ __forceinline__ void upk2(u64 v, float &lo, float &hi) {
    asm("mov.b64 {%0,%1},%2;" : "=f"(lo), "=f"(hi) : "l"(v));
}
__device__ __forceinline__ u64 ffma2(u64 a, u64 b, u64 c) {
    u64 d; asm("fma.rn.f32x2 %0,%1,%2,%3;" : "=l"(d) : "l"(a), "l"(b), "l"(c)); return d;
}

// ---------------- shared-memory access (32-bit addresses) ----------------
__device__ __forceinline__ void lds4f(uint32_t a, float &x, float &y, float &z, float &w) {
    asm volatile("ld.shared.v4.f32 {%0,%1,%2,%3},[%4];"
                 : "=f"(x), "=f"(y), "=f"(z), "=f"(w) : "r"(a));
}
__device__ __forceinline__ void lds2l(uint32_t a, u64 &p, u64 &q) {
    asm volatile("ld.shared.v2.u64 {%0,%1},[%2];" : "=l"(p), "=l"(q) : "r"(a));
}
__device__ __forceinline__ void sts4f(uint32_t a, float x, float y, float z, float w) {
    asm volatile("st.shared.v4.f32 [%0],{%1,%2,%3,%4};"
                 :: "r"(a), "f"(x), "f"(y), "f"(z), "f"(w));
}
__device__ __forceinline__ void sts2l(uint32_t a, u64 p, u64 q) {
    asm volatile("st.shared.v2.u64 [%0],{%1,%2};" :: "r"(a), "l"(p), "l"(q));
}

// Packed XOR swizzle. Buffer = 32 rows x 8 granules(16B). salt = 5*m makes the
// two matrices of a warp occupy disjoint bank groups in every load pattern.
__device__ __forceinline__ uint32_t swz(uint32_t base, int row, int c4, int salt) {
    return base + row * 128 + (((c4 ^ row ^ (row >> 3) ^ salt) & 7) << 4);
}

// ---------------- 32x32 matmul micro-kernels (per 16-thread group) --------
// acc[r][j2] pairs cover output rows 8*it+r, cols 8*jq+2*j2(+1)

// C += P^T-style: C[i][j] = sum_k P[k][i] * Q[k][j]  (both read as rows of k)
__device__ __forceinline__ void mm_rr(uint32_t sp, uint32_t sq, int it, int jq,
                                      int salt, u64 acc[8][4])
{
    #pragma unroll 8
    for (int k = 0; k < 32; k++) {
        float p0,p1,p2,p3,p4,p5,p6,p7;
        lds4f(swz(sp, k, 2*it,     salt), p0, p1, p2, p3);
        lds4f(swz(sp, k, 2*it + 1, salt), p4, p5, p6, p7);
        u64 q0, q1, q2, q3;
        lds2l(swz(sq, k, 2*jq,     salt), q0, q1);
        lds2l(swz(sq, k, 2*jq + 1, salt), q2, q3);
        float ps[8] = {p0,p1,p2,p3,p4,p5,p6,p7};
        #pragma unroll
        for (int r = 0; r < 8; r++) {
            u64 s = pk2(ps[r], ps[r]);
            acc[r][0] = ffma2(s, q0, acc[r][0]);
            acc[r][1] = ffma2(s, q1, acc[r][1]);
            acc[r][2] = ffma2(s, q2, acc[r][2]);
            acc[r][3] = ffma2(s, q3, acc[r][3]);
        }
    }
}

// C += P * Q:  C[i][j] = sum_k P[i][k] * Q[k][j]
// P read as row chunks (float4 over k), Q as rows — no transpose needed.
__device__ __forceinline__ void mm_ck(uint32_t sp, uint32_t sq, int it, int jq,
                                      int salt, u64 acc[8][4])
{
    #pragma unroll 2
    for (int kb = 0; kb < 8; kb++) {
        float p[8][4];
        #pragma unroll
        for (int r = 0; r < 8; r++)
            lds4f(swz(sp, 8*it + r, kb, salt), p[r][0], p[r][1], p[r][2], p[r][3]);
        #pragma unroll
        for (int kk = 0; kk < 4; kk++) {
            int k = 4*kb + kk;
            u64 q0, q1, q2, q3;
            lds2l(swz(sq, k, 2*jq,     salt), q0, q1);
            lds2l(swz(sq, k, 2*jq + 1, salt), q2, q3);
            #pragma unroll
            for (int r = 0; r < 8; r++) {
                u64 s = pk2(p[r][kk], p[r][kk]);
                acc[r][0] = ffma2(s, q0, acc[r][0]);
                acc[r][1] = ffma2(s, q1, acc[r][1]);
                acc[r][2] = ffma2(s, q2, acc[r][2]);
                acc[r][3] = ffma2(s, q3, acc[r][3]);
            }
        }
    }
}

__device__ __forceinline__ void zero_acc(u64 acc[8][4]) {
    #pragma unroll
    for (int r = 0; r < 8; r++)
        #pragma unroll
        for (int q = 0; q < 4; q++) acc[r][q] = 0ull;
}
__device__ __forceinline__ void st_tile(uint32_t s, int it, int jq, int salt, u64 v[8][4]) {
    #pragma unroll
    for (int r = 0; r < 8; r++) {
        sts2l(swz(s, 8*it + r, 2*jq,     salt), v[r][0], v[r][1]);
        sts2l(swz(s, 8*it + r, 2*jq + 1, salt), v[r][2], v[r][3]);
    }
}
__device__ __forceinline__ void ld_tile(uint32_t s, int it, int jq, int salt, u64 v[8][4]) {
    #pragma unroll
    for (int r = 0; r < 8; r++) {
        lds2l(swz(s, 8*it + r, 2*jq,     salt), v[r][0], v[r][1]);
        lds2l(swz(s, 8*it + r, 2*jq + 1, salt), v[r][2], v[r][3]);
    }
}

// ---------------- kernel: 1 warp per block, 2 matrices per warp ----------
__global__ __launch_bounds__(32, 13) void fiber_bundle_kernel(
    const int*   __restrict__ tokens,
    const float* __restrict__ base_w,
    const float* __restrict__ fiber_w,
    const float* __restrict__ conn_w,
    const float* __restrict__ gen,
    float*       __restrict__ out)
{
    __shared__ float smbuf[4096];                 // 16 KB: 2 x (S1 + S2)
    uint32_t sb = (uint32_t)__cvta_generic_to_shared(smbuf);

    const int lane = threadIdx.x;
    const int m    = lane >> 4;                   // matrix in warp: 0/1
    const int t    = lane & 15;
    const int it   = t >> 2;                      // row-tile 0..3
    const int jq   = t & 3;                       // col-tile 0..3
    const int salt = 5 * m;

    const uint32_t S1 = sb + m * 8192;            // X
    const uint32_t S2 = S1 + 4096;                // A / T / T'

    const int tokIdx = blockIdx.x * 2 + m;
    const int tok    = tokens[tokIdx];

    // ---- issue side-copy loads early (overlap with everything) ----
    float4 creg[8];
    {
        const float4* bsrc = (const float4*)(base_w + (size_t)tok * 512);
        #pragma unroll
        for (int j = 0; j < 8; j++) creg[j] = bsrc[t + 16 * j];
    }
    float cv = 0.0f;
    if (t < 8) cv = conn_w[(size_t)tok * 8 + t];
    float4 gv;
    const bool doGen = blockIdx.x < 64;           // 64 blocks x 32 lanes = 2048 float4
    if (doGen) gv = ((const float4*)gen)[blockIdx.x * 32 + lane];

    // ---- load X tile, store swizzled to S1 ----
    {
        const float* fsrc = fiber_w + (size_t)tok * 1024;
        #pragma unroll
        for (int r = 0; r < 8; r++) {
            int row = 8 * it + r;
            float4 a = *(const float4*)(fsrc + row * 32 + 8 * jq);
            float4 b = *(const float4*)(fsrc + row * 32 + 8 * jq + 4);
            sts4f(swz(S1, row, 2*jq,     salt), a.x, a.y, a.z, a.w);
            sts4f(swz(S1, row, 2*jq + 1, salt), b.x, b.y, b.z, b.w);
        }
    }

    // ---- retire side copies ----
    {
        float4* bdst = (float4*)(out + (size_t)tokIdx * 512);
        #pragma unroll
        for (int j = 0; j < 8; j++) bdst[t + 16 * j] = creg[j];
    }
    if (t < 8) out[OUT_CONN + (size_t)tokIdx * 8 + t] = cv;
    if (doGen) ((float4*)(out + OUT_GEN))[blockIdx.x * 32 + lane] = gv;

    __syncwarp();

    u64 acc[8][4];

    // ================= quintic step: X <- X*(15I -10A +3A^2)/8 =============
    // A = X^T X
    zero_acc(acc);
    mm_rr(S1, S1, it, jq, salt, acc);
    st_tile(S2, it, jq, salt, acc);               // S2 = A
    __syncwarp();

    // acc = A^2
    zero_acc(acc);
    mm_ck(S2, S2, it, jq, salt, acc);

    // T = 1.875 I - 1.25 A + 0.375 A^2   (reload own A tile before overwrite)
    {
        u64 at[8][4];
        ld_tile(S2, it, jq, salt, at);
        __syncwarp();                             // all S2 reads complete
        const u64 CB = pk2(-1.25f, -1.25f);
        const u64 CC = pk2( 0.375f, 0.375f);
        #pragma unroll
        for (int r = 0; r < 8; r++)
            #pragma unroll
            for (int j2 = 0; j2 < 4; j2++) {
                float dl = (it == jq && r == 2*j2    ) ? 1.875f : 0.0f;
                float dh = (it == jq && r == 2*j2 + 1) ? 1.875f : 0.0f;
                u64 v = ffma2(at[r][j2], CB, pk2(dl, dh));
                at[r][j2] = ffma2(acc[r][j2], CC, v);
            }
        st_tile(S2, it, jq, salt, at);            // S2 = T
    }
    __syncwarp();

    // X1 = X * T
    zero_acc(acc);
    mm_ck(S1, S2, it, jq, salt, acc);
    __syncwarp();                                 // S1 reads complete
    st_tile(S1, it, jq, salt, acc);               // S1 = X1
    __syncwarp();

    // ================= cubic step: X <- X*(1.5I - 0.5 A) ====================
    zero_acc(acc);
    mm_rr(S1, S1, it, jq, salt, acc);             // acc = A2
    {
        const u64 CH = pk2(-0.5f, -0.5f);
        #pragma unroll
        for (int r = 0; r < 8; r++)
            #pragma unroll
            for (int j2 = 0; j2 < 4; j2++) {
                float dl = (it == jq && r == 2*j2    ) ? 1.5f : 0.0f;
                float dh = (it == jq && r == 2*j2 + 1) ? 1.5f : 0.0f;
                acc[r][j2] = ffma2(acc[r][j2], CH, pk2(dl, dh));
            }
    }
    __syncwarp();                                 // S2 free (previous readers synced)
    st_tile(S2, it, jq, salt, acc);               // S2 = T'
    __syncwarp();

    // final X = X1 * T'
    zero_acc(acc);
    mm_ck(S1, S2, it, jq, salt, acc);

    // ---- write fiber output ----
    {
        float* fdst = out + OUT_FIBER + (size_t)tokIdx * 1024;
        #pragma unroll
        for (int r = 0; r < 8; r++) {
            float x0,x1,x2,x3,x4,x5,x6,x7;
            upk2(acc[r][0], x0, x1);
            upk2(acc[r][1], x2, x3);
            upk2(acc[r][2], x4, x5);
            upk2(acc[r][3], x6, x7);
            float* d = fdst + (8 * it + r) * 32 + 8 * jq;
            *(float4*)d       = make_float4(x0, x1, x2, x3);
            *(float4*)(d + 4) = make_float4(x4, x5, x6, x7);
        }
    }
}

extern "C" void kernel_launch(void* const* d_in, const int* in_sizes, int n_in,
                              void* d_out, int out_size)
{
    const int*   tokens  = (const int*)  d_in[0];
    const float* base_w  = (const float*)d_in[1];
    const float* fiber_w = (const float*)d_in[2];
    const float* conn_w  = (const float*)d_in[3];
    const float* gen     = (const float*)d_in[4];
    float* out = (float*)d_out;

    // prefer max shared-memory carveout so 13 one-warp blocks co-reside
    static bool configured = false;
    if (!configured) {
        cudaFuncSetAttribute(fiber_bundle_kernel,
                             cudaFuncAttributePreferredSharedMemoryCarveout, 100);
        configured = true;
    }

    dim3 grid(NTOK / 2);   // 16384 one-warp blocks, 2 matrices each
    dim3 block(32);
    fiber_bundle_kernel<<<grid, block>>>(tokens, base_w, fiber_w, conn_w, gen, out);
}

// round 4
// speedup vs baseline: 1.2745x; 1.0252x over previous
#include <cuda_runtime.h>
#include <cstdint>

// ---------------- problem constants ----------------
#define NTOK   32768
#define OUT_FIBER  ((size_t)NTOK * 512)
#define OUT_CONN   (OUT_FIBER + (size_t)NTOK * 1024)
#define OUT_GEN    (OUT_CONN + (size_t)NTOK * 8)

typedef unsigned long long u64;

// Normal layout: row stride 144B + 32B per 8-row group. addr(row,col)=row*144+(row>>3)*32+col*4
#define NBUF 4704
// Dup layout: each element stored twice (8B). addr(row,col)=row*384+(row>>2)*16+col*8+(col>>2)*16
#define DBUF 12384
#define SMEM_BYTES (NBUF + DBUF)      // 17088 B -> 13 one-warp blocks/SM

// ---------------- packed fp32x2 / smem helpers ----------------
__device__ __forceinline__ u64 pk2(float lo, float hi) {
    u64 r; asm("mov.b64 %0,{%1,%2};" : "=l"(r) : "f"(lo), "f"(hi)); return r;
}
__device__ __forceinline__ void upk2(u64 v, float &lo, float &hi) {
    asm("mov.b64 {%0,%1},%2;" : "=f"(lo), "=f"(hi) : "l"(v));
}
__device__ __forceinline__ u64 ffma2(u64 a, u64 b, u64 c) {
    u64 d; asm("fma.rn.f32x2 %0,%1,%2,%3;" : "=l"(d) : "l"(a), "l"(b), "l"(c)); return d;
}
__device__ __forceinline__ u64 lds1l(uint32_t a) {
    u64 v; asm volatile("ld.shared.b64 %0,[%1];" : "=l"(v) : "r"(a)); return v;
}
__device__ __forceinline__ void lds2l(uint32_t a, u64 &p, u64 &q) {
    asm volatile("ld.shared.v2.u64 {%0,%1},[%2];" : "=l"(p), "=l"(q) : "r"(a));
}
__device__ __forceinline__ void lds4f(uint32_t a, float &x, float &y, float &z, float &w) {
    asm volatile("ld.shared.v4.f32 {%0,%1,%2,%3},[%4];"
                 : "=f"(x), "=f"(y), "=f"(z), "=f"(w) : "r"(a));
}
__device__ __forceinline__ void sts2l(uint32_t a, u64 p, u64 q) {
    asm volatile("st.shared.v2.u64 [%0],{%1,%2};" :: "r"(a), "l"(p), "l"(q));
}
__device__ __forceinline__ void sts4f(uint32_t a, float x, float y, float z, float w) {
    asm volatile("st.shared.v4.f32 [%0],{%1,%2,%3,%4};"
                 :: "r"(a), "f"(x), "f"(y), "f"(z), "f"(w));
}

// ---------------- FFMA2 4x4-pair core ----------------
__device__ __forceinline__ void fmaGrid(u64 s0, u64 s1, u64 s2, u64 s3,
                                        u64 q0, u64 q1, u64 q2, u64 q3,
                                        u64 acc[4][4])
{
    acc[0][0]=ffma2(s0,q0,acc[0][0]); acc[0][1]=ffma2(s0,q1,acc[0][1]);
    acc[0][2]=ffma2(s0,q2,acc[0][2]); acc[0][3]=ffma2(s0,q3,acc[0][3]);
    acc[1][0]=ffma2(s1,q0,acc[1][0]); acc[1][1]=ffma2(s1,q1,acc[1][1]);
    acc[1][2]=ffma2(s1,q2,acc[1][2]); acc[1][3]=ffma2(s1,q3,acc[1][3]);
    acc[2][0]=ffma2(s2,q0,acc[2][0]); acc[2][1]=ffma2(s2,q1,acc[2][1]);
    acc[2][2]=ffma2(s2,q2,acc[2][2]); acc[2][3]=ffma2(s2,q3,acc[2][3]);
    acc[3][0]=ffma2(s3,q0,acc[3][0]); acc[3][1]=ffma2(s3,q1,acc[3][1]);
    acc[3][2]=ffma2(s3,q2,acc[3][2]); acc[3][3]=ffma2(s3,q3,acc[3][3]);
}

// Type A: C[i][j] = sum_k PD[k][i]*QN[k][j]   (splat from dup rows, bS = Sd + it*48)
__device__ __forceinline__ void mmA(uint32_t bS, uint32_t bQ, u64 acc[4][4]) {
    #pragma unroll 1
    for (int kb = 0; kb < 4; kb++) {
        uint32_t sB = bS + kb * 3104;
        uint32_t qB = bQ + kb * 1184;
        #pragma unroll
        for (int j = 0; j < 8; j++) {
            uint32_t sa = sB + j * 384 + ((j >> 2) << 4);
            u64 s0,s1,s2,s3; lds2l(sa, s0, s1); lds2l(sa + 16, s2, s3);
            uint32_t qa = qB + j * 144;
            u64 q0,q1,q2,q3; lds2l(qa, q0, q1); lds2l(qa + 16, q2, q3);
            fmaGrid(s0,s1,s2,s3, q0,q1,q2,q3, acc);
        }
    }
}

// Type B: C[i][j] = sum_k PD[i][k]*QN[k][j]   (splat along dup cols, bS = Sd + it*1552)
__device__ __forceinline__ void mmB(uint32_t bS, uint32_t bQ, u64 acc[4][4]) {
    #pragma unroll 1
    for (int kb = 0; kb < 4; kb++) {
        uint32_t sB = bS + kb * 96;
        uint32_t qB = bQ + kb * 1184;
        #pragma unroll
        for (int j = 0; j < 8; j++) {
            uint32_t co = sB + j * 8 + ((j >> 2) << 4);
            u64 s0 = lds1l(co);
            u64 s1 = lds1l(co + 384);
            u64 s2 = lds1l(co + 768);
            u64 s3 = lds1l(co + 1152);
            uint32_t qa = qB + j * 144;
            u64 q0,q1,q2,q3; lds2l(qa, q0, q1); lds2l(qa + 16, q2, q3);
            fmaGrid(s0,s1,s2,s3, q0,q1,q2,q3, acc);
        }
    }
}

// Symmetric-square: C[i][j] = sum_k AN[k][i]*AN[k][j]  (splat via movs; bP = Sn + it*16)
__device__ __forceinline__ void mmSym(uint32_t bP, uint32_t bQ, u64 acc[4][4]) {
    #pragma unroll 1
    for (int kb = 0; kb < 4; kb++) {
        uint32_t pB = bP + kb * 1184;
        uint32_t qB = bQ + kb * 1184;
        #pragma unroll
        for (int j = 0; j < 8; j++) {
            float p0,p1,p2,p3; lds4f(pB + j * 144, p0, p1, p2, p3);
            uint32_t qa = qB + j * 144;
            u64 q0,q1,q2,q3; lds2l(qa, q0, q1); lds2l(qa + 16, q2, q3);
            fmaGrid(pk2(p0,p0), pk2(p1,p1), pk2(p2,p2), pk2(p3,p3),
                    q0, q1, q2, q3, acc);
        }
    }
}

__device__ __forceinline__ void zacc(u64 acc[4][4]) {
    #pragma unroll
    for (int r = 0; r < 4; r++)
        #pragma unroll
        for (int c = 0; c < 4; c++) acc[r][c] = 0ull;
}

// ---------------- kernel: 1 warp = 1 matrix ----------------
__global__ __launch_bounds__(32) void fiber_bundle_kernel(
    const int*   __restrict__ tokens,
    const float* __restrict__ base_w,
    const float* __restrict__ fiber_w,
    const float* __restrict__ conn_w,
    const float* __restrict__ gen,
    float*       __restrict__ out)
{
    __shared__ __align__(16) char smraw[SMEM_BYTES];
    const uint32_t Sn = (uint32_t)__cvta_generic_to_shared(smraw);
    const uint32_t Sd = Sn + NBUF;

    const int lane = threadIdx.x;
    const int it   = lane >> 2;          // 0..7 : rows 4*it..4*it+3
    const int jq   = lane & 3;           // 0..3 : cols 8*jq..8*jq+7

    // per-pattern base addresses (computed once; all k/r offsets are immediates)
    const uint32_t bA   = Sd + it * 48;                            // type-A splat
    const uint32_t bB   = Sd + it * 1552;                          // type-B splat
    const uint32_t bQ   = Sn + jq * 32;                            // pair side
    const uint32_t bP2  = Sn + it * 16;                            // sym splat rows
    const uint32_t bNst = Sn + it * 576 + ((it >> 1) << 5) + jq * 32;  // tile rows in normal
    const uint32_t bDst = Sd + it * 1552 + jq * 96;                // tile rows in dup

    const int tokIdx = blockIdx.x;
    const int tok    = tokens[tokIdx];

    // ---- side-copy loads issued early ----
    float4 breg[4];
    {
        const float4* bsrc = (const float4*)(base_w + (size_t)tok * 512);
        #pragma unroll
        for (int j = 0; j < 4; j++) breg[j] = bsrc[lane + 32 * j];
    }
    float cv = 0.0f;
    if (lane < 8) cv = conn_w[(size_t)tok * 8 + lane];
    float4 gv;
    const bool doGen = blockIdx.x < 64;
    if (doGen) gv = ((const float4*)gen)[blockIdx.x * 32 + lane];

    // ---- load fiber tile (rows 4it..4it+3, cols 8jq..8jq+7); store X_n and X_d ----
    {
        const float* fsrc = fiber_w + (size_t)tok * 1024 + 8 * jq;
        #pragma unroll
        for (int r = 0; r < 4; r++) {
            float4 a = *(const float4*)(fsrc + (4 * it + r) * 32);
            float4 b = *(const float4*)(fsrc + (4 * it + r) * 32 + 4);
            sts4f(bNst + r * 144,      a.x, a.y, a.z, a.w);
            sts4f(bNst + r * 144 + 16, b.x, b.y, b.z, b.w);
            uint32_t d = bDst + r * 384;
            sts4f(d,      a.x, a.x, a.y, a.y);
            sts4f(d + 16, a.z, a.z, a.w, a.w);
            sts4f(d + 48, b.x, b.x, b.y, b.y);
            sts4f(d + 64, b.z, b.z, b.w, b.w);
        }
    }

    // ---- retire side copies ----
    {
        float4* bdst = (float4*)(out + (size_t)tokIdx * 512);
        #pragma unroll
        for (int j = 0; j < 4; j++) bdst[lane + 32 * j] = breg[j];
    }
    if (lane < 8) out[OUT_CONN + (size_t)tokIdx * 8 + lane] = cv;
    if (doGen) ((float4*)(out + OUT_GEN))[blockIdx.x * 32 + lane] = gv;

    __syncwarp();

    u64 acc[4][4];

    // ===== (1) A = X^T X =====
    zacc(acc);
    mmA(bA, bQ, acc);
    __syncwarp();                                    // X_n reads done
    #pragma unroll
    for (int r = 0; r < 4; r++) {                    // A -> Rn
        sts2l(bNst + r * 144,      acc[r][0], acc[r][1]);
        sts2l(bNst + r * 144 + 16, acc[r][2], acc[r][3]);
    }
    __syncwarp();

    // ===== (2) S = A*A (A symmetric); T = 1.875I - 1.25A + 0.375S =====
    zacc(acc);
    mmSym(bP2, bQ, acc);
    u64 at[4][4];
    #pragma unroll
    for (int r = 0; r < 4; r++) {                    // reload own A tile
        lds2l(bNst + r * 144,      at[r][0], at[r][1]);
        lds2l(bNst + r * 144 + 16, at[r][2], at[r][3]);
    }
    __syncwarp();                                    // all A reads done
    {
        const u64 CB = pk2(-1.25f, -1.25f);
        const u64 CC = pk2( 0.375f, 0.375f);
        #pragma unroll
        for (int r = 0; r < 4; r++) {
            const int i = 4 * it + r;
            #pragma unroll
            for (int c = 0; c < 4; c++) {
                const int j0 = 8 * jq + 2 * c;
                float dl = (i == j0    ) ? 1.875f : 0.0f;
                float dh = (i == j0 + 1) ? 1.875f : 0.0f;
                u64 v = ffma2(at[r][c], CB, pk2(dl, dh));
                at[r][c] = ffma2(acc[r][c], CC, v);
            }
            sts2l(bNst + r * 144,      at[r][0], at[r][1]);   // T -> Rn
            sts2l(bNst + r * 144 + 16, at[r][2], at[r][3]);
        }
    }
    __syncwarp();

    // ===== (3) X1 = X * T =====
    zacc(acc);
    mmB(bB, bQ, acc);
    __syncwarp();                                    // T + X_d reads done
    #pragma unroll
    for (int r = 0; r < 4; r++) {                    // X1 -> Rn and Rd
        sts2l(bNst + r * 144,      acc[r][0], acc[r][1]);
        sts2l(bNst + r * 144 + 16, acc[r][2], acc[r][3]);
        float x0,x1,x2,x3,x4,x5,x6,x7;
        upk2(acc[r][0], x0, x1); upk2(acc[r][1], x2, x3);
        upk2(acc[r][2], x4, x5); upk2(acc[r][3], x6, x7);
        uint32_t d = bDst + r * 384;
        sts4f(d,      x0, x0, x1, x1);
        sts4f(d + 16, x2, x2, x3, x3);
        sts4f(d + 48, x4, x4, x5, x5);
        sts4f(d + 64, x6, x6, x7, x7);
    }
    __syncwarp();

    // ===== (4) A2 = X1^T X1 ; T' = 1.5I - 0.5 A2 =====
    zacc(acc);
    mmA(bA, bQ, acc);
    __syncwarp();                                    // X1_n reads done
    {
        const u64 CH = pk2(-0.5f, -0.5f);
        #pragma unroll
        for (int r = 0; r < 4; r++) {
            const int i = 4 * it + r;
            #pragma unroll
            for (int c = 0; c < 4; c++) {
                const int j0 = 8 * jq + 2 * c;
                float dl = (i == j0    ) ? 1.5f : 0.0f;
                float dh = (i == j0 + 1) ? 1.5f : 0.0f;
                acc[r][c] = ffma2(acc[r][c], CH, pk2(dl, dh));
            }
            sts2l(bNst + r * 144,      acc[r][0], acc[r][1]);  // T' -> Rn
            sts2l(bNst + r * 144 + 16, acc[r][2], acc[r][3]);
        }
    }
    __syncwarp();

    // ===== (5) Xf = X1 * T' =====
    zacc(acc);
    mmB(bB, bQ, acc);

    // ---- write fiber output ----
    {
        float* fdst = out + OUT_FIBER + (size_t)tokIdx * 1024 + 8 * jq;
        #pragma unroll
        for (int r = 0; r < 4; r++) {
            float x0,x1,x2,x3,x4,x5,x6,x7;
            upk2(acc[r][0], x0, x1); upk2(acc[r][1], x2, x3);
            upk2(acc[r][2], x4, x5); upk2(acc[r][3], x6, x7);
            float* d = fdst + (4 * it + r) * 32;
            *(float4*)d       = make_float4(x0, x1, x2, x3);
            *(float4*)(d + 4) = make_float4(x4, x5, x6, x7);
        }
    }
}

extern "C" void kernel_launch(void* const* d_in, const int* in_sizes, int n_in,
                              void* d_out, int out_size)
{
    const int*   tokens  = (const int*)  d_in[0];
    const float* base_w  = (const float*)d_in[1];
    const float* fiber_w = (const float*)d_in[2];
    const float* conn_w  = (const float*)d_in[3];
    const float* gen     = (const float*)d_in[4];
    float* out = (float*)d_out;

    static bool configured = false;
    if (!configured) {
        cudaFuncSetAttribute(fiber_bundle_kernel,
                             cudaFuncAttributePreferredSharedMemoryCarveout, 100);
        configured = true;
    }

    dim3 grid(NTOK);      // 32768 one-warp blocks, 1 matrix each
    dim3 block(32);
    fiber_bundle_kernel<<<grid, block>>>(tokens, base_w, fiber_w, conn_w, gen, out);
}

// round 6
// speedup vs baseline: 1.7330x; 1.3598x over previous
#include <cuda_runtime.h>
#include <cstdint>

// ---------------- problem constants ----------------
#define NTOK   32768
#define OUT_FIBER  ((size_t)NTOK * 512)
#define OUT_CONN   (OUT_FIBER + (size_t)NTOK * 1024)
#define OUT_GEN    (OUT_CONN + (size_t)NTOK * 8)

typedef unsigned long long u64;

// Layout: off(row) = row*144 + ((row>>3)<<4)  (all multiples of 16 -> vector-LDS legal)
// Buffer = 31*144 + 48 + 128 = 4640 B. Per matrix 2 buffers = 9280 B.
// Matrix 1 gets +16 B salt -> granule shift 5 (odd) -> the two matrices' load
// phases occupy opposite bank-parity classes: conflict-free at warp level.
#define BUFB   4640
#define MATB   (2 * BUFB)              // 9280
#define SMEMB  (2 * MATB + 16)         // 18576 -> 12 one-warp blocks/SM

// ---------------- packed fp32x2 / smem helpers ----------------
__device__ __forceinline__ u64 pk2(float lo, float hi) {
    u64 r; asm("mov.b64 %0,{%1,%2};" : "=l"(r) : "f"(lo), "f"(hi)); return r;
}
__device__ __forceinline__ void upk2(u64 v, float &lo, float &hi) {
    asm("mov.b64 {%0,%1},%2;" : "=f"(lo), "=f"(hi) : "l"(v));
}
__device__ __forceinline__ u64 ffma2(u64 a, u64 b, u64 c) {
    u64 d; asm("fma.rn.f32x2 %0,%1,%2,%3;" : "=l"(d) : "l"(a), "l"(b), "l"(c)); return d;
}
__device__ __forceinline__ void lds4f(uint32_t a, float &x, float &y, float &z, float &w) {
    asm volatile("ld.shared.v4.f32 {%0,%1,%2,%3},[%4];"
                 : "=f"(x), "=f"(y), "=f"(z), "=f"(w) : "r"(a));
}
__device__ __forceinline__ void lds2l(uint32_t a, u64 &p, u64 &q) {
    asm volatile("ld.shared.v2.u64 {%0,%1},[%2];" : "=l"(p), "=l"(q) : "r"(a));
}
__device__ __forceinline__ void sts4f(uint32_t a, float x, float y, float z, float w) {
    asm volatile("st.shared.v4.f32 [%0],{%1,%2,%3,%4};"
                 :: "r"(a), "f"(x), "f"(y), "f"(z), "f"(w));
}
__device__ __forceinline__ void sts2l(uint32_t a, u64 p, u64 q) {
    asm volatile("st.shared.v2.u64 [%0],{%1,%2};" :: "r"(a), "l"(p), "l"(q));
}

// ---------------- mm_rr: acc += P^T * Q over k = 0..31 ----------------
// P, Q pre-offset by lane: P = buf + it*32, Q = buf + jq*32.
// acc[r][c] = fp32x2 pair (cols 8jq+2c, +1) of output row 8it+r.
// Row k base offset: kb*1168 + kk*144   (off(8kb+kk) with kk<8)
__device__ __forceinline__ void mm_rr(uint32_t P, uint32_t Q, u64 acc[8][4]) {
    #pragma unroll 1
    for (int kb = 0; kb < 4; kb++) {
        const uint32_t Pb = P + kb * 1168;
        const uint32_t Qb = Q + kb * 1168;
        #pragma unroll
        for (int kk = 0; kk < 8; kk++) {
            float p0,p1,p2,p3,p4,p5,p6,p7;
            lds4f(Pb + kk * 144,      p0, p1, p2, p3);
            lds4f(Pb + kk * 144 + 16, p4, p5, p6, p7);
            u64 q0, q1, q2, q3;
            lds2l(Qb + kk * 144,      q0, q1);
            lds2l(Qb + kk * 144 + 16, q2, q3);
            float ps[8] = {p0,p1,p2,p3,p4,p5,p6,p7};
            #pragma unroll
            for (int r = 0; r < 8; r++) {
                u64 s = pk2(ps[r], ps[r]);
                acc[r][0] = ffma2(s, q0, acc[r][0]);
                acc[r][1] = ffma2(s, q1, acc[r][1]);
                acc[r][2] = ffma2(s, q2, acc[r][2]);
                acc[r][3] = ffma2(s, q3, acc[r][3]);
            }
        }
    }
}

__device__ __forceinline__ void zacc(u64 acc[8][4]) {
    #pragma unroll
    for (int r = 0; r < 8; r++)
        #pragma unroll
        for (int c = 0; c < 4; c++) acc[r][c] = 0ull;
}

// diagonal pair of v*I at (row 8it+r, colpair 8jq+2c); nonzero iff it==jq
__device__ __forceinline__ u64 dpair(int ondiag, int r, int c, float v) {
    float dl = (ondiag && r == 2 * c    ) ? v : 0.0f;
    float dh = (ondiag && r == 2 * c + 1) ? v : 0.0f;
    return pk2(dl, dh);
}

// ---------------- kernel: 1 warp, 2 matrices (16 lanes each) ----------------
__global__ __launch_bounds__(32) void fiber_bundle_kernel(
    const int*   __restrict__ tokens,
    const float* __restrict__ base_w,
    const float* __restrict__ fiber_w,
    const float* __restrict__ conn_w,
    const float* __restrict__ gen,
    float*       __restrict__ out)
{
    __shared__ __align__(128) char smraw[SMEMB];
    const uint32_t S = (uint32_t)__cvta_generic_to_shared(smraw);

    const int lane = threadIdx.x;
    const int m    = lane >> 4;              // matrix in warp
    const int t    = lane & 15;
    const int it   = t >> 2;                 // row-tile 0..3 (rows 8it..)
    const int jq   = t & 3;                  // col-tile 0..3 (cols 8jq..)

    const uint32_t bufA = S + m * (MATB + 16);  // Xt -> B -> T -> M1 -> T2
    const uint32_t bufB = bufA + BUFB;          // Xn -> X1n

    const uint32_t pA = bufA + it * 32;      // splat operand in bufA
    const uint32_t qA = bufA + jq * 32;      // pair  operand in bufA
    const uint32_t pB = bufB + it * 32;      // splat operand in bufB
    const uint32_t tA = bufA + it * 1168 + jq * 32;   // own tile rows (bufA)
    const uint32_t tB = bufB + it * 1168 + jq * 32;   // own tile rows (bufB)
    const uint32_t xA = bufA + jq * 1168 + it * 32;   // transposed rows (bufA)
    const uint32_t xB = bufB + jq * 1168 + it * 32;   // transposed rows (bufB)
    const int ond = (it == jq);

    const int tokIdx = blockIdx.x * 2 + m;
    const int tok    = tokens[tokIdx];

    // ---- side-copy loads issued early ----
    float4 breg[8];
    {
        const float4* bsrc = (const float4*)(base_w + (size_t)tok * 512);
        #pragma unroll
        for (int j = 0; j < 8; j++) breg[j] = bsrc[t + 16 * j];
    }
    float cv = 0.0f;
    if (t < 8) cv = conn_w[(size_t)tok * 8 + t];
    float4 gv;
    const bool doGen = blockIdx.x < 64;
    if (doGen) gv = ((const float4*)gen)[blockIdx.x * 32 + lane];

    // ---- load 8x8 fiber tile; store Xn -> bufB, Xt -> bufA (free transpose) ----
    {
        const float* fsrc = fiber_w + (size_t)tok * 1024 + 8 * it * 32 + 8 * jq;
        float x[8][8];
        #pragma unroll
        for (int r = 0; r < 8; r++) {
            float4 a = *(const float4*)(fsrc + r * 32);
            float4 b = *(const float4*)(fsrc + r * 32 + 4);
            x[r][0]=a.x; x[r][1]=a.y; x[r][2]=a.z; x[r][3]=a.w;
            x[r][4]=b.x; x[r][5]=b.y; x[r][6]=b.z; x[r][7]=b.w;
        }
        #pragma unroll
        for (int r = 0; r < 8; r++) {        // Xn rows 8it+r
            sts4f(tB + r * 144,      x[r][0], x[r][1], x[r][2], x[r][3]);
            sts4f(tB + r * 144 + 16, x[r][4], x[r][5], x[r][6], x[r][7]);
        }
        #pragma unroll
        for (int cc = 0; cc < 8; cc++) {     // Xt rows 8jq+cc
            sts4f(xA + cc * 144,      x[0][cc], x[1][cc], x[2][cc], x[3][cc]);
            sts4f(xA + cc * 144 + 16, x[4][cc], x[5][cc], x[6][cc], x[7][cc]);
        }
    }

    // ---- retire side copies ----
    {
        float4* bdst = (float4*)(out + (size_t)tokIdx * 512);
        #pragma unroll
        for (int j = 0; j < 8; j++) bdst[t + 16 * j] = breg[j];
    }
    if (t < 8) out[OUT_CONN + (size_t)tokIdx * 8 + t] = cv;
    if (doGen) ((float4*)(out + OUT_GEN))[blockIdx.x * 32 + lane] = gv;

    __syncwarp();

    u64 acc[8][4];

    // ===== (1) B = Xt^T Xt = X X^T =====
    zacc(acc);
    mm_rr(pA, qA, acc);
    __syncwarp();                            // all Xt reads done
    #pragma unroll
    for (int r = 0; r < 8; r++) {            // B -> bufA (own tile)
        sts2l(tA + r * 144,      acc[r][0], acc[r][1]);
        sts2l(tA + r * 144 + 16, acc[r][2], acc[r][3]);
    }
    __syncwarp();

    // ===== (2) S = B*B (B sym); T = 1.875I - 1.25B + 0.375S =====
    zacc(acc);
    mm_rr(pA, qA, acc);
    u64 bt[8][4];
    #pragma unroll
    for (int r = 0; r < 8; r++) {            // reload own B tile
        lds2l(tA + r * 144,      bt[r][0], bt[r][1]);
        lds2l(tA + r * 144 + 16, bt[r][2], bt[r][3]);
    }
    __syncwarp();                            // all B reads done
    {
        const u64 CB = pk2(-1.25f, -1.25f);
        const u64 CC = pk2( 0.375f, 0.375f);
        #pragma unroll
        for (int r = 0; r < 8; r++) {
            u64 t0 = ffma2(bt[r][0], CB, dpair(ond, r, 0, 1.875f));
            u64 t1 = ffma2(bt[r][1], CB, dpair(ond, r, 1, 1.875f));
            u64 t2 = ffma2(bt[r][2], CB, dpair(ond, r, 2, 1.875f));
            u64 t3 = ffma2(bt[r][3], CB, dpair(ond, r, 3, 1.875f));
            t0 = ffma2(acc[r][0], CC, t0);
            t1 = ffma2(acc[r][1], CC, t1);
            t2 = ffma2(acc[r][2], CC, t2);
            t3 = ffma2(acc[r][3], CC, t3);
            sts2l(tA + r * 144,      t0, t1);   // T -> bufA
            sts2l(tA + r * 144 + 16, t2, t3);
        }
    }
    __syncwarp();

    // ===== (3) M1 = Xn^T T = (T X)^T = X1^T  (T symmetric) =====
    zacc(acc);
    mm_rr(pB, qA, acc);
    __syncwarp();                            // Xn + T reads done
    #pragma unroll
    for (int r = 0; r < 8; r++) {            // M1 -> bufA (own tile)
        sts2l(tA + r * 144,      acc[r][0], acc[r][1]);
        sts2l(tA + r * 144 + 16, acc[r][2], acc[r][3]);
    }
    #pragma unroll
    for (int c = 0; c < 4; c++) {            // X1n = M1^T -> bufB (rows 8jq+2c,+1)
        float lo[8], hi[8];
        #pragma unroll
        for (int r = 0; r < 8; r++) upk2(acc[r][c], lo[r], hi[r]);
        const uint32_t a0 = xB + (2 * c) * 144;
        sts4f(a0,             lo[0], lo[1], lo[2], lo[3]);
        sts4f(a0 + 16,        lo[4], lo[5], lo[6], lo[7]);
        sts4f(a0 + 144,       hi[0], hi[1], hi[2], hi[3]);
        sts4f(a0 + 144 + 16,  hi[4], hi[5], hi[6], hi[7]);
    }
    __syncwarp();

    // ===== (4) B2 = M1^T M1 = X1 X1^T ; T2 = 1.5I - 0.5 B2 =====
    zacc(acc);
    mm_rr(pA, qA, acc);
    __syncwarp();                            // M1 reads done
    {
        const u64 CH = pk2(-0.5f, -0.5f);
        #pragma unroll
        for (int r = 0; r < 8; r++) {
            u64 t0 = ffma2(acc[r][0], CH, dpair(ond, r, 0, 1.5f));
            u64 t1 = ffma2(acc[r][1], CH, dpair(ond, r, 1, 1.5f));
            u64 t2 = ffma2(acc[r][2], CH, dpair(ond, r, 2, 1.5f));
            u64 t3 = ffma2(acc[r][3], CH, dpair(ond, r, 3, 1.5f));
            sts2l(tA + r * 144,      t0, t1);   // T2 -> bufA
            sts2l(tA + r * 144 + 16, t2, t3);
        }
    }
    __syncwarp();

    // ===== (5) F = X1n^T T2 = Xf^T ; write Xf to gmem (transposed) =====
    zacc(acc);
    mm_rr(pB, qA, acc);

    {
        float* fdst = out + OUT_FIBER + (size_t)tokIdx * 1024;
        #pragma unroll
        for (int c = 0; c < 4; c++) {
            float lo[8], hi[8];
            #pragma unroll
            for (int r = 0; r < 8; r++) upk2(acc[r][c], lo[r], hi[r]);
            float* r0 = fdst + (8 * jq + 2 * c) * 32 + 8 * it;
            *(float4*)r0       = make_float4(lo[0], lo[1], lo[2], lo[3]);
            *(float4*)(r0 + 4) = make_float4(lo[4], lo[5], lo[6], lo[7]);
            float* r1 = r0 + 32;
            *(float4*)r1       = make_float4(hi[0], hi[1], hi[2], hi[3]);
            *(float4*)(r1 + 4) = make_float4(hi[4], hi[5], hi[6], hi[7]);
        }
    }
}

extern "C" void kernel_launch(void* const* d_in, const int* in_sizes, int n_in,
                              void* d_out, int out_size)
{
    const int*   tokens  = (const int*)  d_in[0];
    const float* base_w  = (const float*)d_in[1];
    const float* fiber_w = (const float*)d_in[2];
    const float* conn_w  = (const float*)d_in[3];
    const float* gen     = (const float*)d_in[4];
    float* out = (float*)d_out;

    static bool configured = false;
    if (!configured) {
        cudaFuncSetAttribute(fiber_bundle_kernel,
                             cudaFuncAttributePreferredSharedMemoryCarveout, 100);
        configured = true;
    }

    dim3 grid(NTOK / 2);   // 16384 one-warp blocks, 2 matrices each
    dim3 block(32);
    fiber_bundle_kernel<<<grid, block>>>(tokens, base_w, fiber_w, conn_w, gen, out);
}